// round 16
// baseline (speedup 1.0000x reference)
#include <cuda_runtime.h>
#include <cuda_fp16.h>
#include <cstdint>

#define BB 32768
#define DD 512
#define EE 10
#define HH 128
#define RH1 256
#define RH2 128
#define ROWS 64                             // rows per CTA tile
#define NBLK (BB / ROWS)                    // 512 row-blocks

// ---- packed fp16 scratch (static __device__ globals: allocation-guard safe) ----
// u32 = half2(v[2k], v[2k+1]) along K. Weights k-major: [kp][n].
__device__ uint32_t g_xtp[(size_t)BB * (DD / 2)];        // x packed   [B][256]
__device__ uint32_t g_hr1p[(size_t)BB * (RH1 / 2)];      // hr1 packed [B][128]
__device__ uint32_t g_w1p[(size_t)(DD / 2) * RH1];       // rw1 packed [256 kp][256 n]
__device__ uint32_t g_w2p[(size_t)(RH1 / 2) * RH2];      // rw2 packed [128 kp][128 n]
__device__ uint32_t g_e1p[(size_t)EE * (DD / 2) * HH];   // we1 packed [10*256 kp][128 n]
__device__ uint32_t g_e2p[(size_t)EE * (HH / 2) * HH];   // we2 packed [10*64 kp][128 n]
__device__ int      g_cnt[NBLK];                         // completion counters

__device__ __forceinline__ uint32_t pkh2(float a, float b) {
    __half2 h = __floats2half2_rn(a, b);
    return *reinterpret_cast<uint32_t*>(&h);
}
__device__ __forceinline__ uint32_t s2u(const void* p) {
    uint32_t a;
    asm("{ .reg .u64 t; cvta.to.shared.u64 t, %1; cvt.u32.u64 %0, t; }" : "=r"(a) : "l"(p));
    return a;
}

// ---- smem geometry (u32). Conflict-free strides mod 32: 36->4, 136->8, 68->4.
#define A_STRIDE 36                        // A tile: 64 rows x 32 kp u32
#define B_STRIDE 136                       // B tile: 32 kp-rows x 128 n u32
#define A_STG (ROWS * A_STRIDE)            // 2304 u32
#define B_STG (32 * B_STRIDE)              // 4352 u32
#define STG_F (A_STG + B_STG)              // 6656 u32 per stage
#define L2B_OFF STG_F                      // expert L2-B single buffer (stage-1 region)
#define H1_STRIDE 68                       // h1 buffer: 64 rows x 64 kp u32 (stage-0 region)
#define MEGA_SMEM (2 * STG_F * 4)          // 53248 B -> 4 CTAs/SM

#define CPA(dst, src) \
    asm volatile("cp.async.cg.shared.global [%0], [%1], 16;" :: "r"(dst), "l"(src) : "memory")
#define CPC() asm volatile("cp.async.commit_group;" ::: "memory")
#define CPW0() asm volatile("cp.async.wait_group 0;" ::: "memory")

#define MMA16(cc, a0, a1, a2, a3, b0, b1) \
    asm volatile("mma.sync.aligned.m16n8k16.row.col.f32.f16.f16.f32 " \
                 "{%0,%1,%2,%3}, {%4,%5,%6,%7}, {%8,%9}, {%0,%1,%2,%3};" \
                 : "+f"(cc[0]), "+f"(cc[1]), "+f"(cc[2]), "+f"(cc[3]) \
                 : "r"(a0), "r"(a1), "r"(a2), "r"(a3), "r"(b0), "r"(b1))

// One 64-k chunk (4 x k16) of a 64x128 CTA tile. 4 warps (2m x 2n), warp
// tile 32x64 (mt=2, nt=8) — proven fragment math from R13.
__device__ __forceinline__ void mma_chunk(
    const uint32_t* __restrict__ AsU, int astride,
    const uint32_t* __restrict__ BsU,
    float (&c)[2][8][4], int warp_m, int warp_n, int grp, int tig)
{
#pragma unroll
    for (int s = 0; s < 4; s++) {
        uint32_t a[2][4];
#pragma unroll
        for (int mt = 0; mt < 2; mt++) {
            const int rb = warp_m * 32 + mt * 16 + grp;
            const int kp = s * 8 + tig;
            a[mt][0] = AsU[rb * astride + kp];
            a[mt][1] = AsU[(rb + 8) * astride + kp];
            a[mt][2] = AsU[rb * astride + kp + 4];
            a[mt][3] = AsU[(rb + 8) * astride + kp + 4];
        }
        uint32_t b[8][2];
#pragma unroll
        for (int nt = 0; nt < 8; nt++) {
            const int nb = warp_n * 64 + nt * 8 + grp;
            b[nt][0] = BsU[(s * 8 + tig) * B_STRIDE + nb];
            b[nt][1] = BsU[(s * 8 + tig + 4) * B_STRIDE + nb];
        }
#pragma unroll
        for (int mt = 0; mt < 2; mt++)
#pragma unroll
            for (int nt = 0; nt < 8; nt++)
                MMA16(c[mt][nt], a[mt][0], a[mt][1], a[mt][2], a[mt][3],
                      b[nt][0], b[nt][1]);
    }
}

// ============================================================================
// Megakernel. grid = (512 row-blocks, 3 roles), 128 threads, 4 CTAs/SM.
//   y=0: experts 0..4 -> chart    y=1: experts 5..9 -> chart
//   y=2: router L1 (2 col tiles) + L2 + logits + gumbel -> wts
// 2-stage cp.async ring, CPW0 (proven). 4 independent barrier domains per SM
// hide each other's load-wait/barrier windows. 3rd finisher computes z.
// ============================================================================
__global__ __launch_bounds__(128, 4) void mega(
    const uint32_t* __restrict__ xtp, const uint32_t* __restrict__ w1p,
    const float* __restrict__ rb1, const uint32_t* __restrict__ w2p,
    const float* __restrict__ rb2, const float* __restrict__ rw3,
    const float* __restrict__ rb3, const float* __restrict__ u,
    const uint32_t* __restrict__ e1p, const float* __restrict__ eb1,
    const uint32_t* __restrict__ e2p, const float* __restrict__ eb2,
    const float* __restrict__ ew3, const float* __restrict__ eb3,
    uint32_t* __restrict__ hr1p, float* __restrict__ wts,
    float* __restrict__ chart, float* __restrict__ z)
{
    extern __shared__ uint32_t smu[];
    __shared__ float zcs[2 * ROWS];     // L3 reduction [64 rows][2]
    __shared__ float ew3s[256];         // ew3[e] slice [128][2]
    __shared__ float eb1s[128];
    __shared__ float eb2s[128];
    __shared__ int s_old;

    const uint32_t smem_base = s2u(smu);
    const int tid = threadIdx.x;
    const int wid = tid >> 5, lane = tid & 31;
    const int grp = lane >> 2, tig = lane & 3;
    const int warp_m = wid & 1, warp_n = wid >> 1;   // 2 x 2 warps, 32x64 tiles
    const int row0 = blockIdx.x * ROWS;
    const int role = (blockIdx.y == 2) ? 0 : (int)blockIdx.y + 1;  // experts first

    // cp.async maps (128 threads): A = 64 rows x 128B (4x16B/thread);
    // B = 32 kp-rows x 512B (8x16B/thread).
    const int arow = tid >> 1, ahalf = tid & 1;
    const int bkrow = tid >> 2, bq = tid & 3;

    float c[2][8][4];

    if (role == 0) {
        // ---------------- ROUTER ----------------
        const uint32_t* Ag = xtp + (long long)(row0 + arow) * (DD / 2);

        // --- R1: two 128-col tiles, K=512 -> 8 chunks of 64k ---
        for (int ct = 0; ct < 2; ct++) {
            auto loadR1 = [&](int i) {
                const uint32_t sA = smem_base + (i & 1) * (STG_F * 4);
                const uint32_t sB = sA + A_STG * 4;
#pragma unroll
                for (int j = 0; j < 4; j++) {
                    const int k4 = ahalf * 4 + j;
                    CPA(sA + arow * 144 + k4 * 16, Ag + i * 32 + k4 * 4);
                }
                const uint32_t* Wg = w1p + (long long)(i * 32 + bkrow) * RH1 + ct * 128;
#pragma unroll
                for (int j = 0; j < 8; j++) {
                    const int c4 = bq + j * 4;
                    CPA(sB + bkrow * (B_STRIDE * 4) + c4 * 16, Wg + c4 * 4);
                }
                CPC();
            };
#pragma unroll
            for (int mt = 0; mt < 2; mt++)
#pragma unroll
                for (int nt = 0; nt < 8; nt++)
#pragma unroll
                    for (int q = 0; q < 4; q++) c[mt][nt][q] = 0.f;

            loadR1(0);
            for (int i = 0; i < 8; i++) {
                CPW0();
                __syncthreads();
                if (i + 1 < 8) loadR1(i + 1);
                const uint32_t* AsU = smu + (i & 1) * STG_F;
                mma_chunk(AsU, A_STRIDE, AsU + A_STG, c, warp_m, warp_n, grp, tig);
            }
            __syncthreads();    // ring drained before next ct reuses it

            // epilogue: hr1p[:, ct half] = pack(relu(c + rb1))
#pragma unroll
            for (int mt = 0; mt < 2; mt++) {
                const int rb = row0 + warp_m * 32 + mt * 16 + grp;
#pragma unroll
                for (int nt = 0; nt < 8; nt++) {
                    const int col = warp_n * 64 + nt * 8 + 2 * tig;   // 0..127
                    const int colp = ct * 64 + (col >> 1);
                    const float b0 = rb1[ct * 128 + col], b1 = rb1[ct * 128 + col + 1];
                    const float v0 = fmaxf(c[mt][nt][0] + b0, 0.f);
                    const float v1 = fmaxf(c[mt][nt][1] + b1, 0.f);
                    const float v2 = fmaxf(c[mt][nt][2] + b0, 0.f);
                    const float v3 = fmaxf(c[mt][nt][3] + b1, 0.f);
                    hr1p[(long long)rb * (RH1 / 2) + colp]       = pkh2(v0, v1);
                    hr1p[(long long)(rb + 8) * (RH1 / 2) + colp] = pkh2(v2, v3);
                }
            }
            __syncthreads();
        }

        // --- R2: K=256 -> 4 chunks, A = hr1p rows ---
        const uint32_t* Ag2 = hr1p + (long long)(row0 + arow) * (RH1 / 2);
        auto loadR2 = [&](int i) {
            const uint32_t sA = smem_base + (i & 1) * (STG_F * 4);
            const uint32_t sB = sA + A_STG * 4;
#pragma unroll
            for (int j = 0; j < 4; j++) {
                const int k4 = ahalf * 4 + j;
                CPA(sA + arow * 144 + k4 * 16, Ag2 + i * 32 + k4 * 4);
            }
            const uint32_t* Wg = w2p + (long long)(i * 32 + bkrow) * RH2;
#pragma unroll
            for (int j = 0; j < 8; j++) {
                const int c4 = bq + j * 4;
                CPA(sB + bkrow * (B_STRIDE * 4) + c4 * 16, Wg + c4 * 4);
            }
            CPC();
        };
#pragma unroll
        for (int mt = 0; mt < 2; mt++)
#pragma unroll
            for (int nt = 0; nt < 8; nt++)
#pragma unroll
                for (int q = 0; q < 4; q++) c[mt][nt][q] = 0.f;

        loadR2(0);
        for (int i = 0; i < 4; i++) {
            CPW0();
            __syncthreads();
            if (i + 1 < 4) loadR2(i + 1);
            const uint32_t* AsU = smu + (i & 1) * STG_F;
            mma_chunk(AsU, A_STRIDE, AsU + A_STG, c, warp_m, warp_n, grp, tig);
        }
        __syncthreads();   // ring drained; overlay w3s/lgs there

        // --- logits: relu(c + rb2) @ rw3, smem atomics ---
        float* w3s = (float*)smu;                   // [RH2][EE]
        float* lgs = (float*)smu + RH2 * EE;        // [64][EE]
        for (int i = tid; i < RH2 * EE; i += 128) w3s[i] = rw3[i];
        for (int i = tid; i < ROWS * EE; i += 128) lgs[i] = 0.f;
        __syncthreads();

#pragma unroll
        for (int mt = 0; mt < 2; mt++) {
            float pl0[EE], pl1[EE];
#pragma unroll
            for (int e = 0; e < EE; e++) { pl0[e] = 0.f; pl1[e] = 0.f; }
#pragma unroll
            for (int nt = 0; nt < 8; nt++) {
                const int col = warp_n * 64 + nt * 8 + 2 * tig;
                const float b0 = rb2[col], b1 = rb2[col + 1];
                const float v0 = fmaxf(c[mt][nt][0] + b0, 0.f);
                const float v1 = fmaxf(c[mt][nt][1] + b1, 0.f);
                const float v2 = fmaxf(c[mt][nt][2] + b0, 0.f);
                const float v3 = fmaxf(c[mt][nt][3] + b1, 0.f);
#pragma unroll
                for (int e = 0; e < EE; e++) {
                    const float w0 = w3s[col * EE + e], w1 = w3s[(col + 1) * EE + e];
                    pl0[e] += v0 * w0 + v1 * w1;
                    pl1[e] += v2 * w0 + v3 * w1;
                }
            }
            const int r = warp_m * 32 + mt * 16 + grp;
#pragma unroll
            for (int e = 0; e < EE; e++) {
                atomicAdd(&lgs[r * EE + e], pl0[e]);
                atomicAdd(&lgs[(r + 8) * EE + e], pl1[e]);
            }
        }
        __syncthreads();

        // --- gumbel softmax -> wts ---
        if (tid < ROWS) {
            const long long row = row0 + tid;
            float lg[EE];
            float m = -1e30f;
#pragma unroll
            for (int e = 0; e < EE; e++) {
                float uu = u[row * EE + e];
                uu = fminf(fmaxf(uu, 1e-10f), 1.0f);
                const float g = -logf(-logf(uu) + 1e-10f);
                lg[e] = (lgs[tid * EE + e] + rb3[e] + g) * (1.0f / 3.0f);
                m = fmaxf(m, lg[e]);
            }
            float s = 0.f;
#pragma unroll
            for (int e = 0; e < EE; e++) { lg[e] = expf(lg[e] - m); s += lg[e]; }
            const float inv = 1.0f / s;
#pragma unroll
            for (int e = 0; e < EE; e++) wts[row * EE + e] = lg[e] * inv;
        }
    } else {
        // ---------------- EXPERTS (5 per block) ----------------
        const int e0 = 5 * (role - 1);
        const uint32_t* Ag = xtp + (long long)(row0 + arow) * (DD / 2);

        auto loadL1 = [&](int e, int i) {
            const uint32_t sA = smem_base + (i & 1) * (STG_F * 4);
            const uint32_t sB = sA + A_STG * 4;
#pragma unroll
            for (int j = 0; j < 4; j++) {
                const int k4 = ahalf * 4 + j;
                CPA(sA + arow * 144 + k4 * 16, Ag + i * 32 + k4 * 4);
            }
            const uint32_t* Wg = e1p + ((long long)e * (DD / 2) + i * 32 + bkrow) * HH;
#pragma unroll
            for (int j = 0; j < 8; j++) {
                const int c4 = bq + j * 4;
                CPA(sB + bkrow * (B_STRIDE * 4) + c4 * 16, Wg + c4 * 4);
            }
            CPC();
        };
        auto loadL2B = [&](int e, int kc) {   // single buffer at stage-1 base
            const uint32_t sB = smem_base + L2B_OFF * 4;
            const uint32_t* Wg = e2p + ((long long)e * (HH / 2) + kc * 32 + bkrow) * HH;
#pragma unroll
            for (int j = 0; j < 8; j++) {
                const int c4 = bq + j * 4;
                CPA(sB + bkrow * (B_STRIDE * 4) + c4 * 16, Wg + c4 * 4);
            }
            CPC();
        };

        loadL1(e0, 0);
        for (int e = e0; e < e0 + 5; e++) {
            eb1s[tid] = eb1[e * HH + tid];
#pragma unroll
            for (int mt = 0; mt < 2; mt++)
#pragma unroll
                for (int nt = 0; nt < 8; nt++)
#pragma unroll
                    for (int q = 0; q < 4; q++) c[mt][nt][q] = 0.f;

            // --- L1: K=512 -> 8 chunks ---
            for (int i = 0; i < 8; i++) {
                CPW0();
                __syncthreads();
                if (i + 1 < 8) loadL1(e, i + 1);
                const uint32_t* AsU = smu + (i & 1) * STG_F;
                mma_chunk(AsU, A_STRIDE, AsU + A_STG, c, warp_m, warp_n, grp, tig);
            }
            __syncthreads();    // chunk-7 (stage 1) reads done
            loadL2B(e, 0);      // overwrite stage-1 region

            // --- h1 packed -> smem (64 x 68 u32, stage-0 region; stage 0 last
            //     read at chunk 6, synced by the barrier above) ---
#pragma unroll
            for (int mt = 0; mt < 2; mt++) {
                const int r = warp_m * 32 + mt * 16 + grp;
#pragma unroll
                for (int nt = 0; nt < 8; nt++) {
                    const int col = warp_n * 64 + nt * 8 + 2 * tig;
                    const int colp = col >> 1;
                    const float b0 = eb1s[col], b1 = eb1s[col + 1];
                    const float v0 = fmaxf(c[mt][nt][0] + b0, 0.f);
                    const float v1 = fmaxf(c[mt][nt][1] + b1, 0.f);
                    const float v2 = fmaxf(c[mt][nt][2] + b0, 0.f);
                    const float v3 = fmaxf(c[mt][nt][3] + b1, 0.f);
                    smu[r * H1_STRIDE + colp]       = pkh2(v0, v1);
                    smu[(r + 8) * H1_STRIDE + colp] = pkh2(v2, v3);
                }
            }

            // --- L2: K=128 -> 2 chunks, A from h1 smem, B single-buffered ---
#pragma unroll
            for (int mt = 0; mt < 2; mt++)
#pragma unroll
                for (int nt = 0; nt < 8; nt++)
#pragma unroll
                    for (int q = 0; q < 4; q++) c[mt][nt][q] = 0.f;

            for (int kc = 0; kc < 2; kc++) {
                CPW0();
                __syncthreads();    // kc=0: also orders h1 writes before reads
                mma_chunk(smu + kc * 32, H1_STRIDE, smu + L2B_OFF, c,
                          warp_m, warp_n, grp, tig);
                __syncthreads();    // B buffer reads done
                if (kc == 0) loadL2B(e, 1);
            }

            if (e + 1 < e0 + 5) loadL1(e + 1, 0);   // stage 0: h1 reads done

            // --- L3: zc = relu(c + eb2) @ ew3[e] -> chart ---
            ew3s[tid]       = ew3[(long long)e * 256 + tid];
            ew3s[tid + 128] = ew3[(long long)e * 256 + tid + 128];
            eb2s[tid] = eb2[e * HH + tid];
            if (tid < 2 * ROWS) zcs[tid] = 0.f;
            __syncthreads();

#pragma unroll
            for (int mt = 0; mt < 2; mt++) {
                float p00 = 0.f, p01 = 0.f, p10 = 0.f, p11 = 0.f;
#pragma unroll
                for (int nt = 0; nt < 8; nt++) {
                    const int col = warp_n * 64 + nt * 8 + 2 * tig;
                    const float b0 = eb2s[col], b1 = eb2s[col + 1];
                    const float v0 = fmaxf(c[mt][nt][0] + b0, 0.f);
                    const float v1 = fmaxf(c[mt][nt][1] + b1, 0.f);
                    const float v2 = fmaxf(c[mt][nt][2] + b0, 0.f);
                    const float v3 = fmaxf(c[mt][nt][3] + b1, 0.f);
                    const float w00 = ew3s[col * 2],       w01 = ew3s[col * 2 + 1];
                    const float w10 = ew3s[(col + 1) * 2], w11 = ew3s[(col + 1) * 2 + 1];
                    p00 += v0 * w00 + v1 * w10;  p01 += v0 * w01 + v1 * w11;
                    p10 += v2 * w00 + v3 * w10;  p11 += v2 * w01 + v3 * w11;
                }
                const int r = warp_m * 32 + mt * 16 + grp;
                atomicAdd(&zcs[r * 2],           p00);
                atomicAdd(&zcs[r * 2 + 1],       p01);
                atomicAdd(&zcs[(r + 8) * 2],     p10);
                atomicAdd(&zcs[(r + 8) * 2 + 1], p11);
            }
            __syncthreads();

            if (tid < ROWS) {
                const long long row = row0 + tid;
                const float zc0 = zcs[tid * 2]     + eb3[e * 2];
                const float zc1 = zcs[tid * 2 + 1] + eb3[e * 2 + 1];
                *(float2*)(chart + ((long long)e * BB + row) * 2) = make_float2(zc0, zc1);
            }
            __syncthreads();   // zcs/ew3s/eb1s reuse next expert
        }
    }

    // ---------------- completion: 3rd finisher computes z ----------------
    __threadfence();
    __syncthreads();
    if (tid == 0) s_old = atomicAdd(&g_cnt[blockIdx.x], 1);
    __syncthreads();
    if (s_old == 2) {
        __threadfence();
        if (tid < ROWS) {
            const long long row = row0 + tid;
            float z0 = 0.f, z1 = 0.f;
#pragma unroll
            for (int e = 0; e < EE; e++) {
                const float w  = __ldcg(&wts[row * EE + e]);
                const float a0 = __ldcg(&chart[((long long)e * BB + row) * 2]);
                const float a1 = __ldcg(&chart[((long long)e * BB + row) * 2 + 1]);
                z0 += w * a0;
                z1 += w * a1;
            }
            *(float2*)(z + row * 2) = make_float2(z0, z1);
        }
    }
}

// ============================================================================
// Convert + k-pairwise pack to fp16 (k-major weights); reset g_cnt.
// ============================================================================
#define XN  (BB * (DD / 2))
#define W1N ((DD / 2) * RH1)
#define W2N ((RH1 / 2) * RH2)
#define E1N (EE * (DD / 2) * HH)
#define E2N (EE * (HH / 2) * HH)
#define TOTN (XN + W1N + W2N + E1N + E2N)

__global__ __launch_bounds__(256) void cvt_all(
    const float2* __restrict__ x2, const float* __restrict__ rw1,
    const float* __restrict__ rw2, const float* __restrict__ ew1,
    const float* __restrict__ ew2,
    uint32_t* __restrict__ xtp, uint32_t* __restrict__ w1p,
    uint32_t* __restrict__ w2p, uint32_t* __restrict__ e1p,
    uint32_t* __restrict__ e2p)
{
    long long i = (long long)blockIdx.x * 256 + threadIdx.x;
    if (i < NBLK) g_cnt[i] = 0;

    if (i < XN) { const float2 v = x2[i]; xtp[i] = pkh2(v.x, v.y); return; }
    i -= XN;
    if (i < W1N) {
        const int kp = (int)(i >> 8), n = (int)(i & 255);
        w1p[i] = pkh2(rw1[(2 * kp) * RH1 + n], rw1[(2 * kp + 1) * RH1 + n]);
        return;
    }
    i -= W1N;
    if (i < W2N) {
        const int kp = (int)(i >> 7), n = (int)(i & 127);
        w2p[i] = pkh2(rw2[(2 * kp) * RH2 + n], rw2[(2 * kp + 1) * RH2 + n]);
        return;
    }
    i -= W2N;
    if (i < E1N) {   // flat kp across experts (512 rows/expert: even, no straddle)
        const long long kp = i >> 7; const int n = (int)(i & 127);
        e1p[i] = pkh2(ew1[(2 * kp) * HH + n], ew1[(2 * kp + 1) * HH + n]);
        return;
    }
    i -= E1N;
    if (i < E2N) {
        const long long kp = i >> 7; const int n = (int)(i & 127);
        e2p[i] = pkh2(ew2[(2 * kp) * HH + n], ew2[(2 * kp + 1) * HH + n]);
    }
}

// ============================================================================
extern "C" void kernel_launch(void* const* d_in, const int* in_sizes, int n_in,
                              void* d_out, int out_size)
{
    const float* x   = (const float*)d_in[0];
    const float* u   = (const float*)d_in[1];
    const float* rw1 = (const float*)d_in[2];
    const float* rb1 = (const float*)d_in[3];
    const float* rw2 = (const float*)d_in[4];
    const float* rb2 = (const float*)d_in[5];
    const float* rw3 = (const float*)d_in[6];
    const float* rb3 = (const float*)d_in[7];
    const float* ew1 = (const float*)d_in[8];
    const float* eb1 = (const float*)d_in[9];
    const float* ew2 = (const float*)d_in[10];
    const float* eb2 = (const float*)d_in[11];
    const float* ew3 = (const float*)d_in[12];
    const float* eb3 = (const float*)d_in[13];

    float* out   = (float*)d_out;
    float* z     = out;                                      // [B, 2]
    float* wts   = out + (size_t)BB * 2;                     // [B, E]
    float* chart = out + (size_t)BB * 2 + (size_t)BB * EE;   // [E, B, 2]

    uint32_t *xtp, *hr1p, *w1p, *w2p, *e1p, *e2p;
    cudaGetSymbolAddress((void**)&xtp, g_xtp);
    cudaGetSymbolAddress((void**)&hr1p, g_hr1p);
    cudaGetSymbolAddress((void**)&w1p, g_w1p);
    cudaGetSymbolAddress((void**)&w2p, g_w2p);
    cudaGetSymbolAddress((void**)&e1p, g_e1p);
    cudaGetSymbolAddress((void**)&e2p, g_e2p);

    cudaFuncSetAttribute(mega, cudaFuncAttributeMaxDynamicSharedMemorySize, MEGA_SMEM);

    cvt_all<<<(TOTN + 255) / 256, 256>>>(
        (const float2*)x, rw1, rw2, ew1, ew2, xtp, w1p, w2p, e1p, e2p);

    mega<<<dim3(NBLK, 3), 128, MEGA_SMEM>>>(
        xtp, w1p, rb1, w2p, rb2, rw3, rb3, u,
        e1p, eb1, e2p, eb2, ew3, eb3, hr1p, wts, chart, z);
}

// round 17
// speedup vs baseline: 1.7352x; 1.7352x over previous
#include <cuda_runtime.h>
#include <cuda_fp16.h>
#include <cstdint>

#define BB 32768
#define DD 512
#define EE 10
#define HH 128
#define RH1 256
#define RH2 128
#define NBLK (BB / 128)                    // 256 row-blocks
#define NUNITS (NBLK + NBLK * EE)          // 256 router + 2560 expert units

// ---- packed fp16 scratch (static __device__ globals: allocation-guard safe) ----
// u32 = half2(v[2k], v[2k+1]) along K. Weights k-major: [kp][n].
__device__ uint32_t g_xtp[(size_t)BB * (DD / 2)];        // x packed   [B][256]
__device__ uint32_t g_hr1p[(size_t)BB * (RH1 / 2)];      // hr1 packed [B][128]
__device__ uint32_t g_w1p[(size_t)(DD / 2) * RH1];       // rw1 packed [256 kp][256 n]
__device__ uint32_t g_w2p[(size_t)(RH1 / 2) * RH2];      // rw2 packed [128 kp][128 n]
__device__ uint32_t g_e1p[(size_t)EE * (DD / 2) * HH];   // we1 packed
__device__ uint32_t g_e2p[(size_t)EE * (HH / 2) * HH];   // we2 packed
__device__ int      g_cnt[NBLK];                         // completion counters (11 each)
__device__ int      g_work;                              // work-stealing queue head

__device__ __forceinline__ uint32_t pkh2(float a, float b) {
    __half2 h = __floats2half2_rn(a, b);
    return *reinterpret_cast<uint32_t*>(&h);
}
__device__ __forceinline__ uint32_t s2u(const void* p) {
    uint32_t a;
    asm("{ .reg .u64 t; cvta.to.shared.u64 t, %1; cvt.u32.u64 %0, t; }" : "=r"(a) : "l"(p));
    return a;
}

// ---- smem geometry (u32 units). Conflict-free strides mod 32: 36->4, 136->8, 68->4.
#define A_STRIDE 36                        // A tile: 128 rows x 32 kp u32
#define B_STRIDE 136                       // B tile: 32 kp-rows x 128 n u32
#define A_STG (128 * A_STRIDE)             // 4608 u32
#define B_STG (32 * B_STRIDE)              // 4352 u32
#define STG_F (A_STG + B_STG)              // 8960 u32 per stage
#define AUX_OFF (2 * STG_F)                // expert L2-B double buffer
#define H1_STRIDE 68                       // h1 packed buffer: 128 rows x 64 kp u32
#define MEGA_SMEM ((AUX_OFF + 2 * B_STG) * 4)   // 106496 B -> 2 CTAs/SM (proven)

#define CPA(dst, src) \
    asm volatile("cp.async.cg.shared.global [%0], [%1], 16;" :: "r"(dst), "l"(src) : "memory")
#define CPC() asm volatile("cp.async.commit_group;" ::: "memory")
#define CPW0() asm volatile("cp.async.wait_group 0;" ::: "memory")

#define MMA16(cc, a0, a1, a2, a3, b0, b1) \
    asm volatile("mma.sync.aligned.m16n8k16.row.col.f32.f16.f16.f32 " \
                 "{%0,%1,%2,%3}, {%4,%5,%6,%7}, {%8,%9}, {%0,%1,%2,%3};" \
                 : "+f"(cc[0]), "+f"(cc[1]), "+f"(cc[2]), "+f"(cc[3]) \
                 : "r"(a0), "r"(a1), "r"(a2), "r"(a3), "r"(b0), "r"(b1))

// One 64-k chunk (4 x k16 steps) of 128x128 CTA-tile MMA work. 8 warps
// (4m x 2n), warp tile 32x64 — proven R13 fragment math.
__device__ __forceinline__ void mma_chunk(
    const uint32_t* __restrict__ AsU, int astride,
    const uint32_t* __restrict__ BsU,
    float (&c)[2][8][4], int warp_m, int warp_n, int grp, int tig)
{
#pragma unroll
    for (int s = 0; s < 4; s++) {
        uint32_t a[2][4];
#pragma unroll
        for (int mt = 0; mt < 2; mt++) {
            const int rb = warp_m * 32 + mt * 16 + grp;
            const int kp = s * 8 + tig;
            a[mt][0] = AsU[rb * astride + kp];
            a[mt][1] = AsU[(rb + 8) * astride + kp];
            a[mt][2] = AsU[rb * astride + kp + 4];
            a[mt][3] = AsU[(rb + 8) * astride + kp + 4];
        }
        uint32_t b[8][2];
#pragma unroll
        for (int nt = 0; nt < 8; nt++) {
            const int nb = warp_n * 64 + nt * 8 + grp;
            b[nt][0] = BsU[(s * 8 + tig) * B_STRIDE + nb];
            b[nt][1] = BsU[(s * 8 + tig + 4) * B_STRIDE + nb];
        }
#pragma unroll
        for (int mt = 0; mt < 2; mt++)
#pragma unroll
            for (int nt = 0; nt < 8; nt++)
                MMA16(c[mt][nt], a[mt][0], a[mt][1], a[mt][2], a[mt][3],
                      b[nt][0], b[nt][1]);
    }
}

// ============================================================================
// Persistent work-stealing megakernel. 592 CTAs (296 effective workers),
// 256 threads, 2 CTAs/SM. Unit queue (longest first):
//   idx 0..255:    router unit (row-block idx): L1 x2 + L2 + logits + gumbel
//   idx 256..2815: expert unit: blk = t/10, e = t%10: L1+L2+L3 -> chart
// 11 contributors per row-block; the 11th finisher computes z.
// ============================================================================
__global__ __launch_bounds__(256, 2) void mega(
    const uint32_t* __restrict__ xtp, const uint32_t* __restrict__ w1p,
    const float* __restrict__ rb1, const uint32_t* __restrict__ w2p,
    const float* __restrict__ rb2, const float* __restrict__ rw3,
    const float* __restrict__ rb3, const float* __restrict__ u,
    const uint32_t* __restrict__ e1p, const float* __restrict__ eb1,
    const uint32_t* __restrict__ e2p, const float* __restrict__ eb2,
    const float* __restrict__ ew3, const float* __restrict__ eb3,
    uint32_t* __restrict__ hr1p, float* __restrict__ wts,
    float* __restrict__ chart, float* __restrict__ z)
{
    extern __shared__ uint32_t smu[];
    __shared__ float zcs[256];
    __shared__ float ew3s[256];
    __shared__ float eb1s[128];
    __shared__ float eb2s[128];
    __shared__ int s_idx;
    __shared__ int s_old;

    const uint32_t smem_base = s2u(smu);
    const int tid = threadIdx.x;
    const int wid = tid >> 5, lane = tid & 31;
    const int grp = lane >> 2, tig = lane & 3;
    const int warp_m = wid & 3, warp_n = wid >> 2;   // 4 x 2 warps, 32x64 tiles
    const int arow = tid >> 1, ahalf = tid & 1;      // A cp.async map
    const int bkrow = tid >> 3, boct = tid & 7;      // B cp.async map

    float c[2][8][4];

    for (;;) {
        __syncthreads();                 // prior unit's smem/s_idx reads done
        if (tid == 0) s_idx = atomicAdd(&g_work, 1);
        __syncthreads();
        const int idx = s_idx;
        if (idx >= NUNITS) break;

        int blk;
        if (idx < NBLK) {
            // ================= ROUTER UNIT =================
            blk = idx;
            const int row0 = blk * 128;
            const uint32_t* Ag = xtp + (long long)(row0 + arow) * (DD / 2);

            for (int ct = 0; ct < 2; ct++) {
                auto loadR1 = [&](int i) {
                    const uint32_t sA = smem_base + (i & 1) * (STG_F * 4);
                    const uint32_t sB = sA + A_STG * 4;
#pragma unroll
                    for (int j = 0; j < 4; j++) {
                        const int k4 = ahalf * 4 + j;
                        CPA(sA + arow * 144 + k4 * 16, Ag + i * 32 + k4 * 4);
                    }
                    const uint32_t* Wg = w1p + (long long)(i * 32 + bkrow) * RH1 + ct * 128;
#pragma unroll
                    for (int j = 0; j < 4; j++) {
                        const int c4 = boct + j * 8;
                        CPA(sB + bkrow * (B_STRIDE * 4) + c4 * 16, Wg + c4 * 4);
                    }
                    CPC();
                };
#pragma unroll
                for (int mt = 0; mt < 2; mt++)
#pragma unroll
                    for (int nt = 0; nt < 8; nt++)
#pragma unroll
                        for (int q = 0; q < 4; q++) c[mt][nt][q] = 0.f;

                loadR1(0);
                for (int i = 0; i < 8; i++) {
                    CPW0();
                    __syncthreads();
                    if (i + 1 < 8) loadR1(i + 1);
                    const uint32_t* AsU = smu + (i & 1) * STG_F;
                    mma_chunk(AsU, A_STRIDE, AsU + A_STG, c, warp_m, warp_n, grp, tig);
                }

                // epilogue: hr1p[:, ct half] = pack(relu(c + rb1))
#pragma unroll
                for (int mt = 0; mt < 2; mt++) {
                    const int rb = row0 + warp_m * 32 + mt * 16 + grp;
#pragma unroll
                    for (int nt = 0; nt < 8; nt++) {
                        const int col = warp_n * 64 + nt * 8 + 2 * tig;
                        const int colp = ct * 64 + (col >> 1);
                        const float b0 = rb1[ct * 128 + col], b1 = rb1[ct * 128 + col + 1];
                        const float v0 = fmaxf(c[mt][nt][0] + b0, 0.f);
                        const float v1 = fmaxf(c[mt][nt][1] + b1, 0.f);
                        const float v2 = fmaxf(c[mt][nt][2] + b0, 0.f);
                        const float v3 = fmaxf(c[mt][nt][3] + b1, 0.f);
                        hr1p[(long long)rb * (RH1 / 2) + colp]       = pkh2(v0, v1);
                        hr1p[(long long)(rb + 8) * (RH1 / 2) + colp] = pkh2(v2, v3);
                    }
                }
                __syncthreads();   // ring drained before next ct / R2
            }

            // --- R2: K=256 -> 4 chunks, A = hr1p rows ---
            const uint32_t* Ag2 = hr1p + (long long)(row0 + arow) * (RH1 / 2);
            auto loadR2 = [&](int i) {
                const uint32_t sA = smem_base + (i & 1) * (STG_F * 4);
                const uint32_t sB = sA + A_STG * 4;
#pragma unroll
                for (int j = 0; j < 4; j++) {
                    const int k4 = ahalf * 4 + j;
                    CPA(sA + arow * 144 + k4 * 16, Ag2 + i * 32 + k4 * 4);
                }
                const uint32_t* Wg = w2p + (long long)(i * 32 + bkrow) * RH2;
#pragma unroll
                for (int j = 0; j < 4; j++) {
                    const int c4 = boct + j * 8;
                    CPA(sB + bkrow * (B_STRIDE * 4) + c4 * 16, Wg + c4 * 4);
                }
                CPC();
            };
#pragma unroll
            for (int mt = 0; mt < 2; mt++)
#pragma unroll
                for (int nt = 0; nt < 8; nt++)
#pragma unroll
                    for (int q = 0; q < 4; q++) c[mt][nt][q] = 0.f;

            loadR2(0);
            for (int i = 0; i < 4; i++) {
                CPW0();
                __syncthreads();
                if (i + 1 < 4) loadR2(i + 1);
                const uint32_t* AsU = smu + (i & 1) * STG_F;
                mma_chunk(AsU, A_STRIDE, AsU + A_STG, c, warp_m, warp_n, grp, tig);
            }
            __syncthreads();   // ring drained; overlay w3s/lgs there

            // --- logits: relu(c + rb2) @ rw3, smem atomics ---
            float* w3s = (float*)smu;                   // [RH2][EE]
            float* lgs = (float*)smu + RH2 * EE;        // [128][EE]
            for (int i = tid; i < RH2 * EE; i += 256) { w3s[i] = rw3[i]; lgs[i] = 0.f; }
            __syncthreads();

#pragma unroll
            for (int mt = 0; mt < 2; mt++) {
                float pl0[EE], pl1[EE];
#pragma unroll
                for (int e = 0; e < EE; e++) { pl0[e] = 0.f; pl1[e] = 0.f; }
#pragma unroll
                for (int nt = 0; nt < 8; nt++) {
                    const int col = warp_n * 64 + nt * 8 + 2 * tig;
                    const float b0 = rb2[col], b1 = rb2[col + 1];
                    const float v0 = fmaxf(c[mt][nt][0] + b0, 0.f);
                    const float v1 = fmaxf(c[mt][nt][1] + b1, 0.f);
                    const float v2 = fmaxf(c[mt][nt][2] + b0, 0.f);
                    const float v3 = fmaxf(c[mt][nt][3] + b1, 0.f);
#pragma unroll
                    for (int e = 0; e < EE; e++) {
                        const float w0 = w3s[col * EE + e], w1 = w3s[(col + 1) * EE + e];
                        pl0[e] += v0 * w0 + v1 * w1;
                        pl1[e] += v2 * w0 + v3 * w1;
                    }
                }
                const int r = warp_m * 32 + mt * 16 + grp;
#pragma unroll
                for (int e = 0; e < EE; e++) {
                    atomicAdd(&lgs[r * EE + e], pl0[e]);
                    atomicAdd(&lgs[(r + 8) * EE + e], pl1[e]);
                }
            }
            __syncthreads();

            // --- gumbel softmax -> wts ---
            if (tid < 128) {
                const long long row = row0 + tid;
                float lg[EE];
                float m = -1e30f;
#pragma unroll
                for (int e = 0; e < EE; e++) {
                    float uu = u[row * EE + e];
                    uu = fminf(fmaxf(uu, 1e-10f), 1.0f);
                    const float g = -logf(-logf(uu) + 1e-10f);
                    lg[e] = (lgs[tid * EE + e] + rb3[e] + g) * (1.0f / 3.0f);
                    m = fmaxf(m, lg[e]);
                }
                float s = 0.f;
#pragma unroll
                for (int e = 0; e < EE; e++) { lg[e] = expf(lg[e] - m); s += lg[e]; }
                const float inv = 1.0f / s;
#pragma unroll
                for (int e = 0; e < EE; e++) wts[row * EE + e] = lg[e] * inv;
            }
        } else {
            // ================= EXPERT UNIT =================
            const int t = idx - NBLK;
            blk = t / EE;
            const int e = t - blk * EE;
            const int row0 = blk * 128;
            const uint32_t* Ag = xtp + (long long)(row0 + arow) * (DD / 2);

            auto loadL1 = [&](int i) {
                const uint32_t sA = smem_base + (i & 1) * (STG_F * 4);
                const uint32_t sB = sA + A_STG * 4;
#pragma unroll
                for (int j = 0; j < 4; j++) {
                    const int k4 = ahalf * 4 + j;
                    CPA(sA + arow * 144 + k4 * 16, Ag + i * 32 + k4 * 4);
                }
                const uint32_t* Wg = e1p + ((long long)e * (DD / 2) + i * 32 + bkrow) * HH;
#pragma unroll
                for (int j = 0; j < 4; j++) {
                    const int c4 = boct + j * 8;
                    CPA(sB + bkrow * (B_STRIDE * 4) + c4 * 16, Wg + c4 * 4);
                }
                CPC();
            };
            auto loadL2B = [&](int kc) {
                const uint32_t sB = smem_base + AUX_OFF * 4 + (kc & 1) * (B_STG * 4);
                const uint32_t* Wg = e2p + ((long long)e * (HH / 2) + kc * 32 + bkrow) * HH;
#pragma unroll
                for (int j = 0; j < 4; j++) {
                    const int c4 = boct + j * 8;
                    CPA(sB + bkrow * (B_STRIDE * 4) + c4 * 16, Wg + c4 * 4);
                }
                CPC();
            };

            eb1s[tid < 128 ? tid : tid - 128] = eb1[e * HH + (tid & 127)];
#pragma unroll
            for (int mt = 0; mt < 2; mt++)
#pragma unroll
                for (int nt = 0; nt < 8; nt++)
#pragma unroll
                    for (int q = 0; q < 4; q++) c[mt][nt][q] = 0.f;

            // --- L1: K=512 -> 8 chunks of 64k ---
            loadL1(0);
            for (int i = 0; i < 8; i++) {
                CPW0();
                __syncthreads();
                if (i + 1 < 8) loadL1(i + 1);
                const uint32_t* AsU = smu + (i & 1) * STG_F;
                mma_chunk(AsU, A_STRIDE, AsU + A_STG, c, warp_m, warp_n, grp, tig);
            }
            loadL2B(0);      // AUX region: disjoint, safe to start now

            // --- h1 packed -> smem (128 x 68 u32, stage-0 region) ---
#pragma unroll
            for (int mt = 0; mt < 2; mt++) {
                const int r = warp_m * 32 + mt * 16 + grp;
#pragma unroll
                for (int nt = 0; nt < 8; nt++) {
                    const int col = warp_n * 64 + nt * 8 + 2 * tig;
                    const int colp = col >> 1;
                    const float b0 = eb1s[col], b1 = eb1s[col + 1];
                    const float v0 = fmaxf(c[mt][nt][0] + b0, 0.f);
                    const float v1 = fmaxf(c[mt][nt][1] + b1, 0.f);
                    const float v2 = fmaxf(c[mt][nt][2] + b0, 0.f);
                    const float v3 = fmaxf(c[mt][nt][3] + b1, 0.f);
                    smu[r * H1_STRIDE + colp]       = pkh2(v0, v1);
                    smu[(r + 8) * H1_STRIDE + colp] = pkh2(v2, v3);
                }
            }

            // --- L2: K=128 -> 2 chunks, A from h1 smem, B double-buffered ---
#pragma unroll
            for (int mt = 0; mt < 2; mt++)
#pragma unroll
                for (int nt = 0; nt < 8; nt++)
#pragma unroll
                    for (int q = 0; q < 4; q++) c[mt][nt][q] = 0.f;

            for (int kc = 0; kc < 2; kc++) {
                CPW0();
                __syncthreads();    // kc=0: orders h1 writes before reads
                if (kc + 1 < 2) loadL2B(kc + 1);
                const uint32_t* BsU = smu + AUX_OFF + (kc & 1) * B_STG;
                mma_chunk(smu + kc * 32, H1_STRIDE, BsU, c, warp_m, warp_n, grp, tig);
            }

            // --- L3: zc = relu(c + eb2) @ ew3[e] -> chart ---
            __syncthreads();
            ew3s[tid] = ew3[(long long)e * 256 + tid];
            if (tid < 128) eb2s[tid] = eb2[e * HH + tid];
            zcs[tid] = 0.f;
            __syncthreads();

#pragma unroll
            for (int mt = 0; mt < 2; mt++) {
                float p00 = 0.f, p01 = 0.f, p10 = 0.f, p11 = 0.f;
#pragma unroll
                for (int nt = 0; nt < 8; nt++) {
                    const int col = warp_n * 64 + nt * 8 + 2 * tig;
                    const float b0 = eb2s[col], b1 = eb2s[col + 1];
                    const float v0 = fmaxf(c[mt][nt][0] + b0, 0.f);
                    const float v1 = fmaxf(c[mt][nt][1] + b1, 0.f);
                    const float v2 = fmaxf(c[mt][nt][2] + b0, 0.f);
                    const float v3 = fmaxf(c[mt][nt][3] + b1, 0.f);
                    const float w00 = ew3s[col * 2],       w01 = ew3s[col * 2 + 1];
                    const float w10 = ew3s[(col + 1) * 2], w11 = ew3s[(col + 1) * 2 + 1];
                    p00 += v0 * w00 + v1 * w10;  p01 += v0 * w01 + v1 * w11;
                    p10 += v2 * w00 + v3 * w10;  p11 += v2 * w01 + v3 * w11;
                }
                const int r = warp_m * 32 + mt * 16 + grp;
                atomicAdd(&zcs[r * 2],           p00);
                atomicAdd(&zcs[r * 2 + 1],       p01);
                atomicAdd(&zcs[(r + 8) * 2],     p10);
                atomicAdd(&zcs[(r + 8) * 2 + 1], p11);
            }
            __syncthreads();

            if (tid < 128) {
                const long long row = row0 + tid;
                const float zc0 = zcs[tid * 2]     + eb3[e * 2];
                const float zc1 = zcs[tid * 2 + 1] + eb3[e * 2 + 1];
                *(float2*)(chart + ((long long)e * BB + row) * 2) = make_float2(zc0, zc1);
            }
        }

        // ------- completion: 11th contributor computes z for row-block -------
        __threadfence();
        __syncthreads();
        if (tid == 0) s_old = atomicAdd(&g_cnt[blk], 1);
        __syncthreads();
        if (s_old == EE) {
            __threadfence();
            if (tid < 128) {
                const long long row = (long long)blk * 128 + tid;
                float z0 = 0.f, z1 = 0.f;
#pragma unroll
                for (int e2 = 0; e2 < EE; e2++) {
                    const float w  = __ldcg(&wts[row * EE + e2]);
                    const float a0 = __ldcg(&chart[((long long)e2 * BB + row) * 2]);
                    const float a1 = __ldcg(&chart[((long long)e2 * BB + row) * 2 + 1]);
                    z0 += w * a0;
                    z1 += w * a1;
                }
                *(float2*)(z + row * 2) = make_float2(z0, z1);
            }
        }
    }
}

// ============================================================================
// Convert + k-pairwise pack to fp16 (k-major weights); reset counters.
// ============================================================================
#define XN  (BB * (DD / 2))
#define W1N ((DD / 2) * RH1)
#define W2N ((RH1 / 2) * RH2)
#define E1N (EE * (DD / 2) * HH)
#define E2N (EE * (HH / 2) * HH)
#define TOTN (XN + W1N + W2N + E1N + E2N)

__global__ __launch_bounds__(256) void cvt_all(
    const float2* __restrict__ x2, const float* __restrict__ rw1,
    const float* __restrict__ rw2, const float* __restrict__ ew1,
    const float* __restrict__ ew2,
    uint32_t* __restrict__ xtp, uint32_t* __restrict__ w1p,
    uint32_t* __restrict__ w2p, uint32_t* __restrict__ e1p,
    uint32_t* __restrict__ e2p)
{
    long long i = (long long)blockIdx.x * 256 + threadIdx.x;
    if (i < NBLK) g_cnt[i] = 0;
    if (i == 0) g_work = 0;

    if (i < XN) { const float2 v = x2[i]; xtp[i] = pkh2(v.x, v.y); return; }
    i -= XN;
    if (i < W1N) {
        const int kp = (int)(i >> 8), n = (int)(i & 255);
        w1p[i] = pkh2(rw1[(2 * kp) * RH1 + n], rw1[(2 * kp + 1) * RH1 + n]);
        return;
    }
    i -= W1N;
    if (i < W2N) {
        const int kp = (int)(i >> 7), n = (int)(i & 127);
        w2p[i] = pkh2(rw2[(2 * kp) * RH2 + n], rw2[(2 * kp + 1) * RH2 + n]);
        return;
    }
    i -= W2N;
    if (i < E1N) {   // flat kp across experts (512 rows/expert: even, no straddle)
        const long long kp = i >> 7; const int n = (int)(i & 127);
        e1p[i] = pkh2(ew1[(2 * kp) * HH + n], ew1[(2 * kp + 1) * HH + n]);
        return;
    }
    i -= E1N;
    if (i < E2N) {
        const long long kp = i >> 7; const int n = (int)(i & 127);
        e2p[i] = pkh2(ew2[(2 * kp) * HH + n], ew2[(2 * kp + 1) * HH + n]);
    }
}

// ============================================================================
extern "C" void kernel_launch(void* const* d_in, const int* in_sizes, int n_in,
                              void* d_out, int out_size)
{
    const float* x   = (const float*)d_in[0];
    const float* u   = (const float*)d_in[1];
    const float* rw1 = (const float*)d_in[2];
    const float* rb1 = (const float*)d_in[3];
    const float* rw2 = (const float*)d_in[4];
    const float* rb2 = (const float*)d_in[5];
    const float* rw3 = (const float*)d_in[6];
    const float* rb3 = (const float*)d_in[7];
    const float* ew1 = (const float*)d_in[8];
    const float* eb1 = (const float*)d_in[9];
    const float* ew2 = (const float*)d_in[10];
    const float* eb2 = (const float*)d_in[11];
    const float* ew3 = (const float*)d_in[12];
    const float* eb3 = (const float*)d_in[13];

    float* out   = (float*)d_out;
    float* z     = out;                                      // [B, 2]
    float* wts   = out + (size_t)BB * 2;                     // [B, E]
    float* chart = out + (size_t)BB * 2 + (size_t)BB * EE;   // [E, B, 2]

    uint32_t *xtp, *hr1p, *w1p, *w2p, *e1p, *e2p;
    cudaGetSymbolAddress((void**)&xtp, g_xtp);
    cudaGetSymbolAddress((void**)&hr1p, g_hr1p);
    cudaGetSymbolAddress((void**)&w1p, g_w1p);
    cudaGetSymbolAddress((void**)&w2p, g_w2p);
    cudaGetSymbolAddress((void**)&e1p, g_e1p);
    cudaGetSymbolAddress((void**)&e2p, g_e2p);

    cudaFuncSetAttribute(mega, cudaFuncAttributeMaxDynamicSharedMemorySize, MEGA_SMEM);

    cvt_all<<<(TOTN + 255) / 256, 256>>>(
        (const float2*)x, rw1, rw2, ew1, ew2, xtp, w1p, w2p, e1p, e2p);

    mega<<<592, 256, MEGA_SMEM>>>(
        xtp, w1p, rb1, w2p, rb2, rw3, rb3, u,
        e1p, eb1, e2p, eb2, ew3, eb3, hr1p, wts, chart, z);
}